// round 11
// baseline (speedup 1.0000x reference)
#include <cuda_runtime.h>
#include <cuda_bf16.h>
#include <math.h>

#define A_TOTAL 36864
#define NIN     6000
#define NOUTB   300
#define BATCH   4
#define NSEL    16384

// output layout (float32, concatenated reference tuple)
#define OFS_SCORES 0
#define OFS_LOCS   294912
#define OFS_ROIS   884736
#define OFS_RIDX   889536
#define OFS_ANCH   890736

#define TSTRIDE (9u * 8u * 512u * 32u)   // u32 elements per split-term plane

// scratch (device globals; no allocation allowed)
__device__ float  g_h[BATCH * 512 * 4096];
__device__ unsigned g_wsplit[3 * 9 * 8 * 512 * 32];   // [term][kk][cic][co][j2] bf16x2
__device__ float4 g_boxes4[BATCH * A_TOTAL];
__device__ unsigned long long g_keys[BATCH * A_TOTAL];
__device__ unsigned g_hist[BATCH * 65536];
__device__ int    g_thr[BATCH];
__device__ int    g_cnt[BATCH];
__device__ unsigned long long g_sel[BATCH * NSEL];
__device__ float4 g_bsort4[BATCH * NIN];
__device__ float  g_areas[BATCH * NIN];
__device__ int    g_keep[BATCH * NIN];

// ---------------------------------------------------------------------------
// helpers
// ---------------------------------------------------------------------------
#define SWZ(o) ((o) ^ (((o) >> 3) & 0x70))

static __device__ __forceinline__ unsigned smem_u32(const void* p) {
    unsigned a;
    asm("{ .reg .u64 t; cvta.to.shared.u64 t, %1; cvt.u32.u64 %0, t; }"
        : "=r"(a) : "l"(p));
    return a;
}
#define STS32(addr, val) \
    asm volatile("st.shared.b32 [%0], %1;" :: "r"(addr), "r"(val) : "memory")

#define LDSM_X4(r0, r1, r2, r3, addr) \
    asm volatile("ldmatrix.sync.aligned.m8n8.x4.shared.b16 {%0,%1,%2,%3}, [%4];" \
                 : "=r"(r0), "=r"(r1), "=r"(r2), "=r"(r3) : "r"(addr))

#define MMA16816(d0, d1, d2, d3, a0, a1, a2, a3, b0, b1) \
    asm volatile("mma.sync.aligned.m16n8k16.row.col.f32.bf16.bf16.f32 " \
                 "{%0,%1,%2,%3}, {%4,%5,%6,%7}, {%8,%9}, {%0,%1,%2,%3};" \
                 : "+f"(d0), "+f"(d1), "+f"(d2), "+f"(d3) \
                 : "r"(a0), "r"(a1), "r"(a2), "r"(a3), "r"(b0), "r"(b1))

static __device__ __forceinline__ void split3(float v, unsigned short o[3]) {
    __nv_bfloat16 b0 = __float2bfloat16_rn(v);
    float f0 = __bfloat162float(b0);
    float r1 = v - f0;
    __nv_bfloat16 b1 = __float2bfloat16_rn(r1);
    float f1 = __bfloat162float(b1);
    __nv_bfloat16 b2 = __float2bfloat16_rn(r1 - f1);
    o[0] = __bfloat16_as_ushort(b0);
    o[1] = __bfloat16_as_ushort(b1);
    o[2] = __bfloat16_as_ushort(b2);
}

// ---------------------------------------------------------------------------
// weight split precompute: w[co][ci][kk] -> 3 bf16 planes [kk][cic][co][j2]
// ---------------------------------------------------------------------------
__global__ void wsplit_kernel(const float* __restrict__ w)
{
    int idx = blockIdx.x * 256 + threadIdx.x;   // 9*8*512*32 = 1,179,648 exact
    int j2  = idx & 31;
    int co  = (idx >> 5) & 511;
    int cic = (idx >> 14) & 7;
    int kk  = idx >> 17;
    if (kk >= 9) return;
    int ci = cic * 64 + j2 * 2;
    float v0 = w[((size_t)co * 512 + ci) * 9 + kk];
    float v1 = w[((size_t)co * 512 + ci + 1) * 9 + kk];
    unsigned short h[3], g[3];
    split3(v0, h);
    split3(v1, g);
    unsigned base = (((unsigned)kk * 8 + cic) * 512 + co) * 32 + j2;
#pragma unroll
    for (int t = 0; t < 3; t++)
        g_wsplit[t * TSTRIDE + base] = (unsigned)h[t] | ((unsigned)g[t] << 16);
}

__global__ void zerohist_kernel()
{
    g_hist[blockIdx.x * 1024 + threadIdx.x] = 0u;
}

// ---------------------------------------------------------------------------
// 3x3 conv 512->512 + bias + relu via mma.sync bf16 6-term emulated-fp32.
// CTA: M=128 co (blockIdx.x), N=128 px = 2 rows of one image (blockIdx.y).
// K loop: 72 chunks of 64 ci at fixed (dy,dx). Double-buffered smem staging.
// Warp tile m64 x n32. RZ-bias mitigation: zero-started partial P per phase
// (phase A = big A0B0 term, phase B = 5 small cross terms), folded into the
// master accumulator with rn FADDs.
// ---------------------------------------------------------------------------
__global__ __launch_bounds__(256, 1) void conv_mma_kernel(
    const float* __restrict__ x, const float* __restrict__ bias)
{
    extern __shared__ __align__(16) char dsm[];
    const unsigned raw  = smem_u32(dsm);
    const unsigned base = (raw + 1023u) & ~1023u;  // 1024-aligned tiles

    const int tid = threadIdx.x;
    const int wid = tid >> 5;
    const int lid = tid & 31;
    const int m0  = blockIdx.x * 128;
    const int b   = blockIdx.y >> 5;
    const int y0  = (blockIdx.y & 31) * 2;
    const float* xb = x + (size_t)b * 512 * 4096;

    const int mh = wid >> 2;            // m-half: 64 co
    const int nq = wid & 3;             // n-quarter: 32 px
    const int rlow = lid & 15;
    const int chalf = (lid >> 4) * 16;

    float acc[4][4][4];
    float P[4][4][4];
#pragma unroll
    for (int i = 0; i < 4; i++)
#pragma unroll
        for (int j = 0; j < 4; j++)
#pragma unroll
            for (int r = 0; r < 4; r++) { acc[i][j][r] = 0.f; P[i][j][r] = 0.f; }

    // buffer set layout (per set, stride 98304): B0,B1,B2 @ 0/16K/32K, A0..A2 @ 48K/64K/80K
    auto stage = [&](int c, int s) {
        const int kk  = c >> 3;
        const int cic = c & 7;
        const int dy  = kk / 3, dx = kk - dy * 3;
        const int ci0 = cic * 64;
        const unsigned sb = base + (unsigned)s * 98304u;
        const unsigned* wp = g_wsplit + (((unsigned)kk * 8 + cic) * 512) * 32;
        for (int idx = tid; idx < 4096; idx += 256) {
            int co = idx >> 5, j2 = idx & 31;
            unsigned off = SWZ((unsigned)(co * 128 + j2 * 4));
            unsigned o = (unsigned)(m0 + co) * 32 + j2;
            STS32(sb + 49152u + off, wp[o]);
            STS32(sb + 65536u + off, wp[o + TSTRIDE]);
            STS32(sb + 81920u + off, wp[o + 2 * TSTRIDE]);
        }
        for (int idx = tid; idx < 4096; idx += 256) {
            int px = idx & 127, j2 = idx >> 7;
            int yy = y0 + (px >> 6) + dy - 1;
            int xx = (px & 63) + dx - 1;
            float v0 = 0.f, v1 = 0.f;
            if ((unsigned)yy < 64u && (unsigned)xx < 64u) {
                const float* sp = xb + ((size_t)(ci0 + j2 * 2) * 64 + yy) * 64 + xx;
                v0 = sp[0];
                v1 = sp[4096];
            }
            unsigned short h0[3], h1[3];
            split3(v0, h0);
            split3(v1, h1);
            unsigned off = SWZ((unsigned)(px * 128 + j2 * 4));
            STS32(sb + off,          (unsigned)h0[0] | ((unsigned)h1[0] << 16));
            STS32(sb + 16384u + off, (unsigned)h0[1] | ((unsigned)h1[1] << 16));
            STS32(sb + 32768u + off, (unsigned)h0[2] | ((unsigned)h1[2] << 16));
        }
    };

    // one k16 step for term pair (Ab, Bb) accumulating into P
    auto k16step = [&](unsigned Ab, unsigned Bb, int ks) {
        unsigned bf[2][4];
#pragma unroll
        for (int bn = 0; bn < 2; bn++) {
            unsigned baddr = Bb +
                SWZ((unsigned)((nq * 32 + bn * 16 + rlow) * 128 + ks * 32 + chalf));
            LDSM_X4(bf[bn][0], bf[bn][1], bf[bn][2], bf[bn][3], baddr);
        }
#pragma unroll
        for (int mt = 0; mt < 4; mt++) {
            unsigned aaddr = Ab +
                SWZ((unsigned)((mh * 64 + mt * 16 + rlow) * 128 + ks * 32 + chalf));
            unsigned a0, a1, a2, a3;
            LDSM_X4(a0, a1, a2, a3, aaddr);
#pragma unroll
            for (int bn = 0; bn < 2; bn++) {
                MMA16816(P[mt][bn*2][0], P[mt][bn*2][1], P[mt][bn*2][2], P[mt][bn*2][3],
                         a0, a1, a2, a3, bf[bn][0], bf[bn][2]);
                MMA16816(P[mt][bn*2+1][0], P[mt][bn*2+1][1], P[mt][bn*2+1][2], P[mt][bn*2+1][3],
                         a0, a1, a2, a3, bf[bn][1], bf[bn][3]);
            }
        }
    };

    auto drain = [&]() {
#pragma unroll
        for (int i = 0; i < 4; i++)
#pragma unroll
            for (int j = 0; j < 4; j++)
#pragma unroll
                for (int r = 0; r < 4; r++) { acc[i][j][r] += P[i][j][r]; P[i][j][r] = 0.f; }
    };

    stage(0, 0);
    __syncthreads();

    for (int c = 0; c < 72; c++) {
        const int s = c & 1;
        if (c + 1 < 72) stage(c + 1, s ^ 1);

        const unsigned sb = base + (unsigned)s * 98304u;
        // phase A: big term A0*B0
#pragma unroll
        for (int ks = 0; ks < 4; ks++)
            k16step(sb + 49152u, sb, ks);
        drain();
        // phase B: small cross terms
        const int TA[5] = {0, 1, 1, 0, 2};
        const int TB[5] = {1, 0, 1, 2, 0};
#pragma unroll
        for (int t = 0; t < 5; t++) {
            const unsigned Ab = sb + 49152u + (unsigned)TA[t] * 16384u;
            const unsigned Bb = sb + (unsigned)TB[t] * 16384u;
#pragma unroll
            for (int ks = 0; ks < 4; ks++)
                k16step(Ab, Bb, ks);
        }
        drain();
        __syncthreads();
    }

    // epilogue: accs -> bias+relu -> smem transpose [co][px] (row stride 132 f32)
    {
        const int gr = lid >> 2;
        const int qc = lid & 3;
#pragma unroll
        for (int mt = 0; mt < 4; mt++) {
#pragma unroll
            for (int hi = 0; hi < 2; hi++) {
                int co_l = mh * 64 + mt * 16 + hi * 8 + gr;
                float bb = bias[m0 + co_l];
                unsigned trow = base + (unsigned)co_l * 528u;
#pragma unroll
                for (int nn = 0; nn < 4; nn++) {
#pragma unroll
                    for (int lo = 0; lo < 2; lo++) {
                        int px = nq * 32 + nn * 8 + qc * 2 + lo;
                        float v = acc[mt][nn][hi * 2 + lo] + bb;
                        v = v > 0.f ? v : 0.f;
                        STS32(trow + (unsigned)px * 4u, __float_as_uint(v));
                    }
                }
            }
        }
    }
    __syncthreads();

    // coalesced write-out: g_h[b][m0+co][y0 + px/64][px%64]
    for (int idx = tid; idx < 4096; idx += 256) {
        int co = idx >> 5;
        int p4 = (idx & 31) * 4;
        unsigned a0, a1, a2, a3;
        asm volatile("ld.shared.v4.b32 {%0,%1,%2,%3}, [%4];"
                     : "=r"(a0), "=r"(a1), "=r"(a2), "=r"(a3)
                     : "r"(base + (unsigned)co * 528u + (unsigned)p4 * 4u));
        float* dst = g_h + (((size_t)b * 512 + m0 + co) * 64 + y0 + (p4 >> 6)) * 64
                     + (p4 & 63);
        *(float4*)dst = make_float4(__uint_as_float(a0), __uint_as_float(a1),
                                    __uint_as_float(a2), __uint_as_float(a3));
    }
}

// ---------------------------------------------------------------------------
// 1x1 heads + softmax fg + box decode + sort keys + score-bucket histogram
// ---------------------------------------------------------------------------
__global__ __launch_bounds__(128) void heads_kernel(
    const float* __restrict__ sw, const float* __restrict__ sb,
    const float* __restrict__ lw, const float* __restrict__ lb,
    float* __restrict__ out)
{
    __shared__ float ws[64 * 54];
    const int tid = threadIdx.x;
    const int pg  = blockIdx.x * 128 + tid;
    const int b   = pg >> 12;
    const int pix = pg & 4095;

    float acc[54];
#pragma unroll
    for (int c = 0; c < 54; c++) acc[c] = 0.f;

    for (int cc = 0; cc < 512; cc += 64) {
        for (int idx = tid; idx < 64 * 54; idx += 128) {
            int ci = idx / 54;
            int c  = idx - ci * 54;
            ws[idx] = (c < 18) ? sw[c * 512 + cc + ci]
                               : lw[(c - 18) * 512 + cc + ci];
        }
        __syncthreads();
#pragma unroll 4
        for (int ci = 0; ci < 64; ci++) {
            float v = g_h[((size_t)(b * 512 + cc + ci)) * 4096 + pix];
#pragma unroll
            for (int c = 0; c < 54; c++) acc[c] += v * ws[ci * 54 + c];
        }
        __syncthreads();
    }

    const int y  = pix >> 6;
    const int xq = pix & 63;
    const float sy = (float)(y * 16);
    const float sx = (float)(xq * 16);

#pragma unroll
    for (int k = 0; k < 9; k++) {
        const double RR[3] = {0.5, 1.0, 2.0};
        const double SS[3] = {8.0, 16.0, 32.0};
        double rr = RR[k / 3], ss = SS[k % 3];
        double hh = 16.0 * ss * sqrt(rr);
        double wd = 16.0 * ss * sqrt(1.0 / rr);
        float by1 = (float)(8.0 - hh * 0.5), bx1 = (float)(8.0 - wd * 0.5);
        float by2 = (float)(8.0 + hh * 0.5), bx2 = (float)(8.0 + wd * 0.5);
        float ay1 = sy + by1, ax1 = sx + bx1, ay2 = sy + by2, ax2 = sx + bx2;

        const int a = pix * 9 + k;
        if (b == 0) {
            float* ap = out + OFS_ANCH + (size_t)a * 4;
            ap[0] = ay1; ap[1] = ax1; ap[2] = ay2; ap[3] = ax2;
        }

        float s0 = acc[k * 2 + 0] + sb[k * 2 + 0];
        float s1 = acc[k * 2 + 1] + sb[k * 2 + 1];
        out[OFS_SCORES + (size_t)b * 73728 + (size_t)a * 2 + 0] = s0;
        out[OFS_SCORES + (size_t)b * 73728 + (size_t)a * 2 + 1] = s1;

        float d0 = acc[18 + k * 4 + 0] + lb[k * 4 + 0];
        float d1 = acc[18 + k * 4 + 1] + lb[k * 4 + 1];
        float d2 = acc[18 + k * 4 + 2] + lb[k * 4 + 2];
        float d3 = acc[18 + k * 4 + 3] + lb[k * 4 + 3];
        float* lp = out + OFS_LOCS + (size_t)b * 147456 + (size_t)a * 4;
        lp[0] = d0; lp[1] = d1; lp[2] = d2; lp[3] = d3;

        float ah = ay2 - ay1, aw = ax2 - ax1;
        float cy = ay1 + 0.5f * ah, cx = ax1 + 0.5f * aw;
        float cty = d0 * ah + cy, ctx = d1 * aw + cx;
        float th = expf(d2) * ah, tw = expf(d3) * aw;
        float cy1 = fminf(fmaxf(cty - 0.5f * th, 0.f), 1024.f);
        float cy2 = fminf(fmaxf(cty + 0.5f * th, 0.f), 1024.f);
        float cx1 = fminf(fmaxf(ctx - 0.5f * tw, 0.f), 1024.f);
        float cx2 = fminf(fmaxf(ctx + 0.5f * tw, 0.f), 1024.f);
        bool valid = (cy2 - cy1 >= 16.f) && (cx2 - cx1 >= 16.f);

        float m = fmaxf(s0, s1);
        float e0 = expf(s0 - m), e1 = expf(s1 - m);
        float p1 = e1 / (e0 + e1);

        g_boxes4[(size_t)b * A_TOTAL + a] = make_float4(cy1, cx1, cy2, cx2);

        unsigned long long key;
        if (valid) {
            unsigned u = __float_as_uint(p1);
            u = (u & 0x80000000u) ? ~u : (u | 0x80000000u);
            key = ((unsigned long long)(~u) << 32) | (unsigned)a;
        } else {
            key = (0xFF800000ull << 32) | (unsigned)a;  // -inf score
        }
        g_keys[(size_t)b * A_TOTAL + a] = key;
        atomicAdd(&g_hist[b * 65536 + (unsigned)(key >> 48)], 1u);
    }
}

// find bucket threshold covering rank NIN; also reset count + pad sel buffer
__global__ __launch_bounds__(1024) void select_kernel()
{
    const int b = blockIdx.x, tid = threadIdx.x;
    __shared__ int part[1024];
    const unsigned* h = g_hist + b * 65536;
    int s = 0;
    for (int k = 0; k < 64; k++) s += (int)h[tid * 64 + k];
    part[tid] = s;
    __syncthreads();
    for (int off = 1; off < 1024; off <<= 1) {
        int v = (tid >= off) ? part[tid - off] : 0;
        __syncthreads();
        part[tid] += v;
        __syncthreads();
    }
    int incl = part[tid];
    int excl = incl - s;
    if (excl < NIN && incl >= NIN) {
        int c = excl, T = tid * 64 + 63;
        for (int k = 0; k < 64; k++) {
            c += (int)h[tid * 64 + k];
            if (c >= NIN) { T = tid * 64 + k; break; }
        }
        g_thr[b] = T;
    }
    if (tid == 0) g_cnt[b] = 0;
    for (int i = tid; i < NSEL; i += 1024) g_sel[b * NSEL + i] = ~0ull;
}

__global__ void compact_sel_kernel()
{
    int i = blockIdx.x * 256 + threadIdx.x;
    int b = blockIdx.y;
    if (i >= A_TOTAL) return;
    unsigned long long key = g_keys[(size_t)b * A_TOTAL + i];
    if ((int)(unsigned)(key >> 48) <= g_thr[b]) {
        int p = atomicAdd(&g_cnt[b], 1);
        if (p < NSEL) g_sel[b * NSEL + p] = key;
    }
}

// per-batch smem bitonic sort of <=16384 selected keys, then gather top-6000
__global__ __launch_bounds__(1024) void sortsel_kernel()
{
    const int b = blockIdx.x, tid = threadIdx.x;
    extern __shared__ unsigned long long s[];
    for (int i = tid; i < NSEL; i += 1024) s[i] = g_sel[b * NSEL + i];
    __syncthreads();
    for (int k = 2; k <= NSEL; k <<= 1) {
        for (int j = k >> 1; j > 0; j >>= 1) {
            for (int t = tid; t < NSEL; t += 1024) {
                int ixj = t ^ j;
                if (ixj > t) {
                    unsigned long long A = s[t], B = s[ixj];
                    bool up = ((t & k) == 0);
                    if ((A > B) == up) { s[t] = B; s[ixj] = A; }
                }
            }
            __syncthreads();
        }
    }
    for (int i = tid; i < NIN; i += 1024) {
        unsigned long long key = s[i];
        unsigned idx = (unsigned)key;
        float4 bx = g_boxes4[(size_t)b * A_TOTAL + idx];
        g_bsort4[b * NIN + i] = bx;
        g_areas[b * NIN + i] = (bx.z - bx.x) * (bx.w - bx.y);
        g_keep[b * NIN + i] = (int)((key >> 63) == 0);
    }
}

// sequential greedy NMS, all-smem + register-resident owned boxes
__global__ __launch_bounds__(1024) void nms_kernel()
{
    const int b = blockIdx.x, tid = threadIdx.x;
    extern __shared__ char nsm[];
    float4* bsh = (float4*)nsm;                          // 96000 B
    float* ash = (float*)(nsm + 96000);                  // 24000 B
    unsigned char* ksh = (unsigned char*)(nsm + 120000); // 6000 B

    for (int i = tid; i < NIN; i += 1024) {
        bsh[i] = g_bsort4[b * NIN + i];
        ash[i] = g_areas[b * NIN + i];
        ksh[i] = (unsigned char)g_keep[b * NIN + i];
    }
    __syncthreads();

    float4 myb[6]; float mya[6]; int myk[6];
#pragma unroll
    for (int e = 0; e < 6; e++) {
        int j = tid * 6 + e;
        if (j < NIN) { myb[e] = bsh[j]; mya[e] = ash[j]; myk[e] = (int)ksh[j]; }
        else myk[e] = 0;
    }

    for (int i = 0; i < NIN - 1; i++) {
        if (ksh[i]) {
            float4 bi = bsh[i];
            float ai = ash[i];
#pragma unroll
            for (int e = 0; e < 6; e++) {
                int j = tid * 6 + e;
                if (myk[e] && j > i) {
                    float yy1 = fmaxf(bi.x, myb[e].x);
                    float xx1 = fmaxf(bi.y, myb[e].y);
                    float yy2 = fminf(bi.z, myb[e].z);
                    float xx2 = fminf(bi.w, myb[e].w);
                    float inter = fmaxf(yy2 - yy1, 0.f) * fmaxf(xx2 - xx1, 0.f);
                    float iou = inter / (ai + mya[e] - inter + 1e-9f);
                    if (iou > 0.7f) { myk[e] = 0; ksh[j] = 0; }
                }
            }
            __syncthreads();
        }
    }
    for (int i = tid; i < NIN; i += 1024) g_keep[b * NIN + i] = (int)ksh[i];
}

// compact kept boxes into first 300 rows; zero-fill the rest; roi_indices
__global__ __launch_bounds__(1024) void compact_kernel(float* __restrict__ out)
{
    const int b = blockIdx.x;
    const int tid = threadIdx.x;
    __shared__ int csum[1024];

    const int base = tid * 6;
    int local[6];
    int cnt = 0;
#pragma unroll
    for (int e = 0; e < 6; e++) {
        int i = base + e;
        int k = (i < NIN) ? g_keep[b * NIN + i] : 0;
        local[e] = k;
        cnt += k;
    }
    csum[tid] = cnt;
    __syncthreads();
    for (int off = 1; off < 1024; off <<= 1) {
        int v = (tid >= off) ? csum[tid - off] : 0;
        __syncthreads();
        csum[tid] += v;
        __syncthreads();
    }
    int rank = csum[tid] - cnt;

    float* rois = out + OFS_ROIS + (size_t)b * 1200;
    for (int i = tid; i < 1200; i += 1024) rois[i] = 0.f;
    float* ridx = out + OFS_RIDX + (size_t)b * 300;
    for (int i = tid; i < 300; i += 1024) ridx[i] = (float)b;
    __syncthreads();

    int r = rank;
#pragma unroll
    for (int e = 0; e < 6; e++) {
        int i = base + e;
        if (i < NIN && local[e]) {
            if (r < NOUTB) {
                float4 bx = g_bsort4[b * NIN + i];
                rois[r * 4 + 0] = bx.x;
                rois[r * 4 + 1] = bx.y;
                rois[r * 4 + 2] = bx.z;
                rois[r * 4 + 3] = bx.w;
            }
            r++;
        }
    }
}

extern "C" void kernel_launch(void* const* d_in, const int* in_sizes, int n_in,
                              void* d_out, int out_size)
{
    const float* x       = (const float*)d_in[0];
    const float* conv_w  = (const float*)d_in[1];
    const float* conv_b  = (const float*)d_in[2];
    const float* score_w = (const float*)d_in[3];
    const float* score_b = (const float*)d_in[4];
    const float* loc_w   = (const float*)d_in[5];
    const float* loc_b   = (const float*)d_in[6];
    float* out = (float*)d_out;

    const int CONV_SMEM = 1024 + 2 * 98304;   // align slack + 2 buffer sets
    cudaFuncSetAttribute(conv_mma_kernel,
        cudaFuncAttributeMaxDynamicSharedMemorySize, CONV_SMEM);
    cudaFuncSetAttribute(sortsel_kernel,
        cudaFuncAttributeMaxDynamicSharedMemorySize, NSEL * 8);
    cudaFuncSetAttribute(nms_kernel,
        cudaFuncAttributeMaxDynamicSharedMemorySize, 126016);

    wsplit_kernel<<<4608, 256>>>(conv_w);
    zerohist_kernel<<<256, 1024>>>();
    conv_mma_kernel<<<dim3(4, 128), 256, CONV_SMEM>>>(x, conv_b);
    heads_kernel<<<128, 128>>>(score_w, score_b, loc_w, loc_b, out);
    select_kernel<<<BATCH, 1024>>>();
    compact_sel_kernel<<<dim3(144, BATCH), 256>>>();
    sortsel_kernel<<<BATCH, 1024, NSEL * 8>>>();
    nms_kernel<<<BATCH, 1024, 126016>>>();
    compact_kernel<<<BATCH, 1024>>>(out);
}